// round 2
// baseline (speedup 1.0000x reference)
#include <cuda_runtime.h>
#include <math.h>

#define T_PTS 524288
#define NPER  32768
#define BG    16
#define CIN   16
#define D     32
#define NH    4
#define HD    8
#define NL    2
#define RPTS  16   // points per thread in reduce kernel

// 64 MB scratch for h, tiled: tile of 32 points, channel-major within tile:
// h(point p, chan c) at g_h[(p>>5)*1024 + c*32 + (p&31)]
__device__ float g_h[(size_t)T_PTS * D];
__device__ float g_kv[NL * BG * NH * HD * HD];   // 8192
__device__ float g_ks[NL * BG * NH * HD];        // 1024

__device__ __forceinline__ float phi(float x) {
    // elu(x)+1
    return x > 0.f ? x + 1.f : __expf(x);
}

__device__ __forceinline__ void fma4(float4& a, float s, const float4 w) {
    a.x += s * w.x; a.y += s * w.y; a.z += s * w.z; a.w += s * w.w;
}

// ---------------- stem: h = x@w_in + b_in + pos@w_pos + b_pos ----------------
__global__ __launch_bounds__(256) void stem_kernel(
    const float* __restrict__ x, const float* __restrict__ pos,
    const float* __restrict__ w_in, const float* __restrict__ b_in,
    const float* __restrict__ w_pos, const float* __restrict__ b_pos)
{
    __shared__ __align__(16) float s_win[CIN * D];
    __shared__ __align__(16) float s_wpos[4 * D];   // 3 rows used
    __shared__ __align__(16) float s_b[D];
    int tid = threadIdx.x;
    for (int i = tid; i < CIN * D; i += 256) s_win[i] = w_in[i];
    if (tid < 3 * D) s_wpos[tid] = w_pos[tid];
    if (tid < D)     s_b[tid]    = b_in[tid] + b_pos[tid];
    if (blockIdx.x == 0) {
        for (int i = tid; i < NL*BG*NH*HD*HD; i += 256) g_kv[i] = 0.f;
        for (int i = tid; i < NL*BG*NH*HD;    i += 256) g_ks[i] = 0.f;
    }
    __syncthreads();

    int t = blockIdx.x * 256 + tid;
    const float4* xp = (const float4*)(x + (size_t)t * CIN);
    float xx[CIN];
    #pragma unroll
    for (int i = 0; i < 4; i++) {
        float4 v = xp[i];
        xx[4*i+0] = v.x; xx[4*i+1] = v.y; xx[4*i+2] = v.z; xx[4*i+3] = v.w;
    }
    const float* pp = pos + (size_t)t * 3;
    float p3[3] = { pp[0], pp[1], pp[2] };

    float4 acc[8];
    const float4* b4 = (const float4*)s_b;
    #pragma unroll
    for (int j = 0; j < 8; j++) acc[j] = b4[j];

    const float4* w4 = (const float4*)s_win;      // [i*8 + j4]
    #pragma unroll
    for (int i = 0; i < CIN; i++) {
        float hi = xx[i];
        #pragma unroll
        for (int j = 0; j < 8; j++) fma4(acc[j], hi, w4[i*8 + j]);
    }
    const float4* wp4 = (const float4*)s_wpos;    // [i*8 + j4]
    #pragma unroll
    for (int i = 0; i < 3; i++) {
        float pi = p3[i];
        #pragma unroll
        for (int j = 0; j < 8; j++) fma4(acc[j], pi, wp4[i*8 + j]);
    }

    float* dst = g_h + ((size_t)(t >> 5) << 10) + (t & 31);
    #pragma unroll
    for (int j = 0; j < 8; j++) {
        dst[(4*j+0)*32] = acc[j].x;
        dst[(4*j+1)*32] = acc[j].y;
        dst[(4*j+2)*32] = acc[j].z;
        dst[(4*j+3)*32] = acc[j].w;
    }
}

// ---------------- reduce: kv[cloud][head] += k^T v ; ksum += k ----------------
__global__ __launch_bounds__(256) void reduce_kernel(
    const float* __restrict__ wk, const float* __restrict__ bk,
    const float* __restrict__ wv, const float* __restrict__ bv, int l)
{
    int head = blockIdx.y;
    __shared__ __align__(16) float s_wk[D * HD];
    __shared__ __align__(16) float s_wv[D * HD];
    __shared__ __align__(16) float s_bk[HD];
    __shared__ __align__(16) float s_bv[HD];
    int tid = threadIdx.x;
    if (tid < D * HD) {
        int i = tid / HD, j = tid % HD;
        s_wk[tid] = wk[l*D*D + i*D + head*HD + j];
        s_wv[tid] = wv[l*D*D + i*D + head*HD + j];
    }
    if (tid < HD) { s_bk[tid] = bk[l*D + head*HD + tid];
                    s_bv[tid] = bv[l*D + head*HD + tid]; }
    __syncthreads();

    int base  = blockIdx.x * (256 * RPTS);
    int cloud = blockIdx.x >> 3;   // 4096 points/block, 32768/cloud

    float kv[HD][HD];
    float ks[HD];
    #pragma unroll
    for (int a = 0; a < HD; a++) {
        ks[a] = 0.f;
        #pragma unroll
        for (int b = 0; b < HD; b++) kv[a][b] = 0.f;
    }

    const float4* wk4 = (const float4*)s_wk;   // [i*2 + j4]
    const float4* wv4 = (const float4*)s_wv;
    float4 bk0 = ((const float4*)s_bk)[0], bk1 = ((const float4*)s_bk)[1];
    float4 bv0 = ((const float4*)s_bv)[0], bv1 = ((const float4*)s_bv)[1];

    for (int it = 0; it < RPTS; it++) {
        int p = base + it * 256 + tid;
        const float* hp = g_h + ((size_t)(p >> 5) << 10) + (p & 31);
        float h[D];
        #pragma unroll
        for (int c = 0; c < D; c++) h[c] = hp[c * 32];

        float4 ka0 = bk0, ka1 = bk1, va0 = bv0, va1 = bv1;
        #pragma unroll
        for (int i = 0; i < D; i++) {
            float hi = h[i];
            fma4(ka0, hi, wk4[i*2+0]); fma4(ka1, hi, wk4[i*2+1]);
            fma4(va0, hi, wv4[i*2+0]); fma4(va1, hi, wv4[i*2+1]);
        }
        float kk[8] = { phi(ka0.x), phi(ka0.y), phi(ka0.z), phi(ka0.w),
                        phi(ka1.x), phi(ka1.y), phi(ka1.z), phi(ka1.w) };
        float vv[8] = { va0.x, va0.y, va0.z, va0.w, va1.x, va1.y, va1.z, va1.w };
        #pragma unroll
        for (int a = 0; a < 8; a++) {
            ks[a] += kk[a];
            #pragma unroll
            for (int b = 0; b < 8; b++) kv[a][b] += kk[a] * vv[b];
        }
    }

    // butterfly warp reduce + global atomics (lane 0)
    unsigned mask = 0xffffffffu;
    int lane = tid & 31;
    float* kvg = g_kv + ((size_t)((l*BG + cloud)*NH + head)) * 64;
    float* ksg = g_ks + ((size_t)((l*BG + cloud)*NH + head)) * 8;
    #pragma unroll
    for (int a = 0; a < 8; a++) {
        float s = ks[a];
        #pragma unroll
        for (int off = 16; off; off >>= 1) s += __shfl_xor_sync(mask, s, off);
        if (lane == 0) atomicAdd(&ksg[a], s);
        #pragma unroll
        for (int b = 0; b < 8; b++) {
            float v = kv[a][b];
            #pragma unroll
            for (int off = 16; off; off >>= 1) v += __shfl_xor_sync(mask, v, off);
            if (lane == 0) atomicAdd(&kvg[a*8 + b], v);
        }
    }
}

// ---------------- apply: q, attention, o-proj, LN1, FFN, LN2 ----------------
__global__ __launch_bounds__(256) void apply_kernel(
    const float* __restrict__ wq, const float* __restrict__ bq,
    const float* __restrict__ wo, const float* __restrict__ bo,
    const float* __restrict__ g1, const float* __restrict__ be1,
    const float* __restrict__ w1, const float* __restrict__ bf1,
    const float* __restrict__ w2, const float* __restrict__ bf2,
    const float* __restrict__ g2, const float* __restrict__ be2,
    int l, float* __restrict__ outp)
{
    __shared__ __align__(16) float s_wq[D*D];
    __shared__ __align__(16) float s_wo[D*D];
    __shared__ __align__(16) float s_w1[D*2*D];
    __shared__ __align__(16) float s_w2[2*D*D];
    __shared__ __align__(16) float s_kv[NH*HD*HD];
    __shared__ __align__(16) float s_ks[NH*HD];
    __shared__ __align__(16) float s_bq[D], s_bo[D], s_bf2[D];
    __shared__ __align__(16) float s_bf1[2*D];
    __shared__ __align__(16) float s_g1[D], s_be1[D], s_g2[D], s_be2[D];

    int tid = threadIdx.x;
    int t = blockIdx.x * 256 + tid;
    int cloud = t >> 15;

    for (int i = tid; i < 1024; i += 256) { s_wq[i] = wq[l*1024 + i]; s_wo[i] = wo[l*1024 + i]; }
    for (int i = tid; i < 2048; i += 256) { s_w1[i] = w1[l*2048 + i]; s_w2[i] = w2[l*2048 + i]; }
    if (tid < 32) {
        s_bq[tid]  = bq[l*32 + tid];  s_bo[tid]  = bo[l*32 + tid];
        s_bf2[tid] = bf2[l*32 + tid];
        s_g1[tid]  = g1[l*32 + tid];  s_be1[tid] = be1[l*32 + tid];
        s_g2[tid]  = g2[l*32 + tid];  s_be2[tid] = be2[l*32 + tid];
        s_ks[tid]  = g_ks[(size_t)(l*BG + cloud)*32 + tid];
    }
    if (tid < 64)  s_bf1[tid] = bf1[l*64 + tid];
    s_kv[tid] = g_kv[(size_t)(l*BG + cloud)*256 + tid];   // 256 entries
    __syncthreads();

    const float* hp = g_h + ((size_t)(t >> 5) << 10) + (t & 31);
    float h[D];
    #pragma unroll
    for (int c = 0; c < D; c++) h[c] = hp[c * 32];

    // q = phi(h @ wq + bq)
    float q[D];
    const float4* wq4 = (const float4*)s_wq;   // [c*8 + j4]
    #pragma unroll
    for (int j4 = 0; j4 < 8; j4++) {
        float4 a = ((const float4*)s_bq)[j4];
        #pragma unroll
        for (int c = 0; c < D; c++) fma4(a, h[c], wq4[c*8 + j4]);
        q[4*j4+0] = phi(a.x); q[4*j4+1] = phi(a.y);
        q[4*j4+2] = phi(a.z); q[4*j4+3] = phi(a.w);
    }

    // per-head attention: o = (q @ kv) / (q . ksum + eps)
    float o[D];
    #pragma unroll
    for (int hh = 0; hh < NH; hh++) {
        float zden = 1e-6f;
        #pragma unroll
        for (int d = 0; d < HD; d++) zden += q[hh*8 + d] * s_ks[hh*8 + d];
        float z = __fdividef(1.f, zden);
        const float4* kv4 = (const float4*)(s_kv + hh*64);  // [d*2 + e4]
        float4 a0 = {0,0,0,0}, a1 = {0,0,0,0};
        #pragma unroll
        for (int d = 0; d < HD; d++) {
            float qd = q[hh*8 + d];
            fma4(a0, qd, kv4[d*2+0]); fma4(a1, qd, kv4[d*2+1]);
        }
        o[hh*8+0] = a0.x*z; o[hh*8+1] = a0.y*z; o[hh*8+2] = a0.z*z; o[hh*8+3] = a0.w*z;
        o[hh*8+4] = a1.x*z; o[hh*8+5] = a1.y*z; o[hh*8+6] = a1.z*z; o[hh*8+7] = a1.w*z;
    }

    // o-proj + residual
    float r[D];
    const float4* wo4 = (const float4*)s_wo;   // [j*8 + c4]
    #pragma unroll
    for (int c4 = 0; c4 < 8; c4++) {
        float4 a = ((const float4*)s_bo)[c4];
        #pragma unroll
        for (int j = 0; j < D; j++) fma4(a, o[j], wo4[j*8 + c4]);
        r[4*c4+0] = h[4*c4+0] + a.x; r[4*c4+1] = h[4*c4+1] + a.y;
        r[4*c4+2] = h[4*c4+2] + a.z; r[4*c4+3] = h[4*c4+3] + a.w;
    }

    // LN1
    float mu = 0.f;
    #pragma unroll
    for (int c = 0; c < D; c++) mu += r[c];
    mu *= (1.f / D);
    float var = 0.f;
    #pragma unroll
    for (int c = 0; c < D; c++) { float d0 = r[c] - mu; var += d0 * d0; }
    var *= (1.f / D);
    float rs = rsqrtf(var + 1e-5f);
    float h1[D];
    #pragma unroll
    for (int c = 0; c < D; c++) h1[c] = (r[c] - mu) * rs * s_g1[c] + s_be1[c];

    // FFN: relu(h1 @ w1 + bf1) @ w2 + bf2
    float4 f[8];
    #pragma unroll
    for (int c4 = 0; c4 < 8; c4++) f[c4] = ((const float4*)s_bf2)[c4];
    const float4* w14 = (const float4*)s_w1;   // [c*16 + j4]
    const float4* w24 = (const float4*)s_w2;   // [j*8 + c4]
    #pragma unroll
    for (int j4 = 0; j4 < 16; j4++) {
        float4 a = ((const float4*)s_bf1)[j4];
        #pragma unroll
        for (int c = 0; c < D; c++) fma4(a, h1[c], w14[c*16 + j4]);
        float hid[4] = { fmaxf(a.x, 0.f), fmaxf(a.y, 0.f),
                         fmaxf(a.z, 0.f), fmaxf(a.w, 0.f) };
        #pragma unroll
        for (int u = 0; u < 4; u++) {
            int j = j4*4 + u;
            float hv = hid[u];
            #pragma unroll
            for (int c4 = 0; c4 < 8; c4++) fma4(f[c4], hv, w24[j*8 + c4]);
        }
    }
    float r2[D];
    #pragma unroll
    for (int c4 = 0; c4 < 8; c4++) {
        r2[4*c4+0] = h1[4*c4+0] + f[c4].x; r2[4*c4+1] = h1[4*c4+1] + f[c4].y;
        r2[4*c4+2] = h1[4*c4+2] + f[c4].z; r2[4*c4+3] = h1[4*c4+3] + f[c4].w;
    }

    // LN2
    float mu2 = 0.f;
    #pragma unroll
    for (int c = 0; c < D; c++) mu2 += r2[c];
    mu2 *= (1.f / D);
    float var2 = 0.f;
    #pragma unroll
    for (int c = 0; c < D; c++) { float d0 = r2[c] - mu2; var2 += d0 * d0; }
    var2 *= (1.f / D);
    float rs2 = rsqrtf(var2 + 1e-5f);
    float out[D];
    #pragma unroll
    for (int c = 0; c < D; c++) out[c] = (r2[c] - mu2) * rs2 * s_g2[c] + s_be2[c];

    if (outp) {
        float4* op = (float4*)(outp + (size_t)t * D);
        #pragma unroll
        for (int c4 = 0; c4 < 8; c4++) {
            float4 v = { out[4*c4+0], out[4*c4+1], out[4*c4+2], out[4*c4+3] };
            op[c4] = v;
        }
    } else {
        float* dst = g_h + ((size_t)(t >> 5) << 10) + (t & 31);
        #pragma unroll
        for (int c = 0; c < D; c++) dst[c * 32] = out[c];
    }
}

extern "C" void kernel_launch(void* const* d_in, const int* in_sizes, int n_in,
                              void* d_out, int out_size)
{
    const float* x     = (const float*)d_in[0];
    const float* pos   = (const float*)d_in[1];
    // d_in[2] = batch (int32), trivially t / NPER — unused
    const float* w_in  = (const float*)d_in[3];
    const float* b_in  = (const float*)d_in[4];
    const float* w_pos = (const float*)d_in[5];
    const float* b_pos = (const float*)d_in[6];
    const float* wq    = (const float*)d_in[7];
    const float* bq    = (const float*)d_in[8];
    const float* wk    = (const float*)d_in[9];
    const float* bk    = (const float*)d_in[10];
    const float* wv    = (const float*)d_in[11];
    const float* bv    = (const float*)d_in[12];
    const float* wo    = (const float*)d_in[13];
    const float* bo    = (const float*)d_in[14];
    const float* g1    = (const float*)d_in[15];
    const float* be1   = (const float*)d_in[16];
    const float* w1    = (const float*)d_in[17];
    const float* bf1   = (const float*)d_in[18];
    const float* w2    = (const float*)d_in[19];
    const float* bf2   = (const float*)d_in[20];
    const float* g2    = (const float*)d_in[21];
    const float* be2   = (const float*)d_in[22];

    stem_kernel<<<T_PTS/256, 256>>>(x, pos, w_in, b_in, w_pos, b_pos);
    for (int l = 0; l < NL; l++) {
        reduce_kernel<<<dim3(T_PTS/(256*RPTS), NH), 256>>>(wk, bk, wv, bv, l);
        apply_kernel<<<T_PTS/256, 256>>>(wq, bq, wo, bo, g1, be1, w1, bf1,
                                         w2, bf2, g2, be2, l,
                                         (l == NL-1) ? (float*)d_out : nullptr);
    }
}

// round 3
// speedup vs baseline: 1.0038x; 1.0038x over previous
#include <cuda_runtime.h>
#include <math.h>

#define T_PTS 524288
#define NPER  32768
#define BG    16
#define CIN   16
#define D     32
#define NH    4
#define HD    8
#define NL    2
#define RPTS  16   // points per thread in reduce kernel

// 64 MB scratch for h, tiled: tile of 32 points, channel-major within tile:
// h(point p, chan c) at g_h[(p>>5)*1024 + c*32 + (p&31)]
__device__ float g_h[(size_t)T_PTS * D];
__device__ float g_kv[NL * BG * NH * HD * HD];   // 8192
__device__ float g_ks[NL * BG * NH * HD];        // 1024

__device__ __forceinline__ float phi(float x) {
    // elu(x)+1
    return x > 0.f ? x + 1.f : __expf(x);
}

__device__ __forceinline__ void fma4(float4& a, float s, const float4 w) {
    a.x += s * w.x; a.y += s * w.y; a.z += s * w.z; a.w += s * w.w;
}

// ---------------- stem: h = x@w_in + b_in + pos@w_pos + b_pos ----------------
__global__ __launch_bounds__(256) void stem_kernel(
    const float* __restrict__ x, const float* __restrict__ pos,
    const float* __restrict__ w_in, const float* __restrict__ b_in,
    const float* __restrict__ w_pos, const float* __restrict__ b_pos)
{
    __shared__ __align__(16) float s_win[CIN * D];
    __shared__ __align__(16) float s_wpos[4 * D];   // 3 rows used
    __shared__ __align__(16) float s_b[D];
    int tid = threadIdx.x;
    for (int i = tid; i < CIN * D; i += 256) s_win[i] = w_in[i];
    if (tid < 3 * D) s_wpos[tid] = w_pos[tid];
    if (tid < D)     s_b[tid]    = b_in[tid] + b_pos[tid];
    if (blockIdx.x == 0) {
        for (int i = tid; i < NL*BG*NH*HD*HD; i += 256) g_kv[i] = 0.f;
        for (int i = tid; i < NL*BG*NH*HD;    i += 256) g_ks[i] = 0.f;
    }
    __syncthreads();

    int t = blockIdx.x * 256 + tid;
    const float4* xp = (const float4*)(x + (size_t)t * CIN);
    float xx[CIN];
    #pragma unroll
    for (int i = 0; i < 4; i++) {
        float4 v = xp[i];
        xx[4*i+0] = v.x; xx[4*i+1] = v.y; xx[4*i+2] = v.z; xx[4*i+3] = v.w;
    }
    const float* pp = pos + (size_t)t * 3;
    float p3[3] = { pp[0], pp[1], pp[2] };

    float4 acc[8];
    const float4* b4 = (const float4*)s_b;
    #pragma unroll
    for (int j = 0; j < 8; j++) acc[j] = b4[j];

    const float4* w4 = (const float4*)s_win;      // [i*8 + j4]
    #pragma unroll
    for (int i = 0; i < CIN; i++) {
        float hi = xx[i];
        #pragma unroll
        for (int j = 0; j < 8; j++) fma4(acc[j], hi, w4[i*8 + j]);
    }
    const float4* wp4 = (const float4*)s_wpos;    // [i*8 + j4]
    #pragma unroll
    for (int i = 0; i < 3; i++) {
        float pi = p3[i];
        #pragma unroll
        for (int j = 0; j < 8; j++) fma4(acc[j], pi, wp4[i*8 + j]);
    }

    float* dst = g_h + ((size_t)(t >> 5) << 10) + (t & 31);
    #pragma unroll
    for (int j = 0; j < 8; j++) {
        dst[(4*j+0)*32] = acc[j].x;
        dst[(4*j+1)*32] = acc[j].y;
        dst[(4*j+2)*32] = acc[j].z;
        dst[(4*j+3)*32] = acc[j].w;
    }
}

// ---------------- reduce: kv[cloud][head] += k^T v ; ksum += k ----------------
__global__ __launch_bounds__(256) void reduce_kernel(
    const float* __restrict__ wk, const float* __restrict__ bk,
    const float* __restrict__ wv, const float* __restrict__ bv, int l)
{
    int head = blockIdx.y;
    __shared__ __align__(16) float s_wk[D * HD];
    __shared__ __align__(16) float s_wv[D * HD];
    __shared__ __align__(16) float s_bk[HD];
    __shared__ __align__(16) float s_bv[HD];
    int tid = threadIdx.x;
    if (tid < D * HD) {
        int i = tid / HD, j = tid % HD;
        s_wk[tid] = wk[l*D*D + i*D + head*HD + j];
        s_wv[tid] = wv[l*D*D + i*D + head*HD + j];
    }
    if (tid < HD) { s_bk[tid] = bk[l*D + head*HD + tid];
                    s_bv[tid] = bv[l*D + head*HD + tid]; }
    __syncthreads();

    int base  = blockIdx.x * (256 * RPTS);
    int cloud = blockIdx.x >> 3;   // 4096 points/block, 32768/cloud

    float kv[HD][HD];
    float ks[HD];
    #pragma unroll
    for (int a = 0; a < HD; a++) {
        ks[a] = 0.f;
        #pragma unroll
        for (int b = 0; b < HD; b++) kv[a][b] = 0.f;
    }

    const float4* wk4 = (const float4*)s_wk;   // [i*2 + j4]
    const float4* wv4 = (const float4*)s_wv;
    float4 bk0 = ((const float4*)s_bk)[0], bk1 = ((const float4*)s_bk)[1];
    float4 bv0 = ((const float4*)s_bv)[0], bv1 = ((const float4*)s_bv)[1];

    for (int it = 0; it < RPTS; it++) {
        int p = base + it * 256 + tid;
        const float* hp = g_h + ((size_t)(p >> 5) << 10) + (p & 31);
        float h[D];
        #pragma unroll
        for (int c = 0; c < D; c++) h[c] = hp[c * 32];

        float4 ka0 = bk0, ka1 = bk1, va0 = bv0, va1 = bv1;
        #pragma unroll
        for (int i = 0; i < D; i++) {
            float hi = h[i];
            fma4(ka0, hi, wk4[i*2+0]); fma4(ka1, hi, wk4[i*2+1]);
            fma4(va0, hi, wv4[i*2+0]); fma4(va1, hi, wv4[i*2+1]);
        }
        float kk[8] = { phi(ka0.x), phi(ka0.y), phi(ka0.z), phi(ka0.w),
                        phi(ka1.x), phi(ka1.y), phi(ka1.z), phi(ka1.w) };
        float vv[8] = { va0.x, va0.y, va0.z, va0.w, va1.x, va1.y, va1.z, va1.w };
        #pragma unroll
        for (int a = 0; a < 8; a++) {
            ks[a] += kk[a];
            #pragma unroll
            for (int b = 0; b < 8; b++) kv[a][b] += kk[a] * vv[b];
        }
    }

    // butterfly warp reduce + global atomics (lane 0)
    unsigned mask = 0xffffffffu;
    int lane = tid & 31;
    float* kvg = g_kv + ((size_t)((l*BG + cloud)*NH + head)) * 64;
    float* ksg = g_ks + ((size_t)((l*BG + cloud)*NH + head)) * 8;
    #pragma unroll
    for (int a = 0; a < 8; a++) {
        float s = ks[a];
        #pragma unroll
        for (int off = 16; off; off >>= 1) s += __shfl_xor_sync(mask, s, off);
        if (lane == 0) atomicAdd(&ksg[a], s);
        #pragma unroll
        for (int b = 0; b < 8; b++) {
            float v = kv[a][b];
            #pragma unroll
            for (int off = 16; off; off >>= 1) v += __shfl_xor_sync(mask, v, off);
            if (lane == 0) atomicAdd(&kvg[a*8 + b], v);
        }
    }
}

// ---------------- apply: q, attention, o-proj, LN1, FFN, LN2 ----------------
__global__ __launch_bounds__(256) void apply_kernel(
    const float* __restrict__ wq, const float* __restrict__ bq,
    const float* __restrict__ wo, const float* __restrict__ bo,
    const float* __restrict__ g1, const float* __restrict__ be1,
    const float* __restrict__ w1, const float* __restrict__ bf1,
    const float* __restrict__ w2, const float* __restrict__ bf2,
    const float* __restrict__ g2, const float* __restrict__ be2,
    int l, float* __restrict__ outp)
{
    __shared__ __align__(16) float s_wq[D*D];
    __shared__ __align__(16) float s_wo[D*D];
    __shared__ __align__(16) float s_w1[D*2*D];
    __shared__ __align__(16) float s_w2[2*D*D];
    __shared__ __align__(16) float s_kv[NH*HD*HD];
    __shared__ __align__(16) float s_ks[NH*HD];
    __shared__ __align__(16) float s_bq[D], s_bo[D], s_bf2[D];
    __shared__ __align__(16) float s_bf1[2*D];
    __shared__ __align__(16) float s_g1[D], s_be1[D], s_g2[D], s_be2[D];

    int tid = threadIdx.x;
    int t = blockIdx.x * 256 + tid;
    int cloud = t >> 15;

    for (int i = tid; i < 1024; i += 256) { s_wq[i] = wq[l*1024 + i]; s_wo[i] = wo[l*1024 + i]; }
    for (int i = tid; i < 2048; i += 256) { s_w1[i] = w1[l*2048 + i]; s_w2[i] = w2[l*2048 + i]; }
    if (tid < 32) {
        s_bq[tid]  = bq[l*32 + tid];  s_bo[tid]  = bo[l*32 + tid];
        s_bf2[tid] = bf2[l*32 + tid];
        s_g1[tid]  = g1[l*32 + tid];  s_be1[tid] = be1[l*32 + tid];
        s_g2[tid]  = g2[l*32 + tid];  s_be2[tid] = be2[l*32 + tid];
        s_ks[tid]  = g_ks[(size_t)(l*BG + cloud)*32 + tid];
    }
    if (tid < 64)  s_bf1[tid] = bf1[l*64 + tid];
    s_kv[tid] = g_kv[(size_t)(l*BG + cloud)*256 + tid];   // 256 entries
    __syncthreads();

    const float* hp = g_h + ((size_t)(t >> 5) << 10) + (t & 31);
    float h[D];
    #pragma unroll
    for (int c = 0; c < D; c++) h[c] = hp[c * 32];

    // q = phi(h @ wq + bq)
    float q[D];
    const float4* wq4 = (const float4*)s_wq;   // [c*8 + j4]
    #pragma unroll
    for (int j4 = 0; j4 < 8; j4++) {
        float4 a = ((const float4*)s_bq)[j4];
        #pragma unroll
        for (int c = 0; c < D; c++) fma4(a, h[c], wq4[c*8 + j4]);
        q[4*j4+0] = phi(a.x); q[4*j4+1] = phi(a.y);
        q[4*j4+2] = phi(a.z); q[4*j4+3] = phi(a.w);
    }

    // per-head attention: o = (q @ kv) / (q . ksum + eps)
    float o[D];
    #pragma unroll
    for (int hh = 0; hh < NH; hh++) {
        float zden = 1e-6f;
        #pragma unroll
        for (int d = 0; d < HD; d++) zden += q[hh*8 + d] * s_ks[hh*8 + d];
        float z = __fdividef(1.f, zden);
        const float4* kv4 = (const float4*)(s_kv + hh*64);  // [d*2 + e4]
        float4 a0 = {0,0,0,0}, a1 = {0,0,0,0};
        #pragma unroll
        for (int d = 0; d < HD; d++) {
            float qd = q[hh*8 + d];
            fma4(a0, qd, kv4[d*2+0]); fma4(a1, qd, kv4[d*2+1]);
        }
        o[hh*8+0] = a0.x*z; o[hh*8+1] = a0.y*z; o[hh*8+2] = a0.z*z; o[hh*8+3] = a0.w*z;
        o[hh*8+4] = a1.x*z; o[hh*8+5] = a1.y*z; o[hh*8+6] = a1.z*z; o[hh*8+7] = a1.w*z;
    }

    // o-proj + residual
    float r[D];
    const float4* wo4 = (const float4*)s_wo;   // [j*8 + c4]
    #pragma unroll
    for (int c4 = 0; c4 < 8; c4++) {
        float4 a = ((const float4*)s_bo)[c4];
        #pragma unroll
        for (int j = 0; j < D; j++) fma4(a, o[j], wo4[j*8 + c4]);
        r[4*c4+0] = h[4*c4+0] + a.x; r[4*c4+1] = h[4*c4+1] + a.y;
        r[4*c4+2] = h[4*c4+2] + a.z; r[4*c4+3] = h[4*c4+3] + a.w;
    }

    // LN1
    float mu = 0.f;
    #pragma unroll
    for (int c = 0; c < D; c++) mu += r[c];
    mu *= (1.f / D);
    float var = 0.f;
    #pragma unroll
    for (int c = 0; c < D; c++) { float d0 = r[c] - mu; var += d0 * d0; }
    var *= (1.f / D);
    float rs = rsqrtf(var + 1e-5f);
    float h1[D];
    #pragma unroll
    for (int c = 0; c < D; c++) h1[c] = (r[c] - mu) * rs * s_g1[c] + s_be1[c];

    // FFN: relu(h1 @ w1 + bf1) @ w2 + bf2
    float4 f[8];
    #pragma unroll
    for (int c4 = 0; c4 < 8; c4++) f[c4] = ((const float4*)s_bf2)[c4];
    const float4* w14 = (const float4*)s_w1;   // [c*16 + j4]
    const float4* w24 = (const float4*)s_w2;   // [j*8 + c4]
    #pragma unroll
    for (int j4 = 0; j4 < 16; j4++) {
        float4 a = ((const float4*)s_bf1)[j4];
        #pragma unroll
        for (int c = 0; c < D; c++) fma4(a, h1[c], w14[c*16 + j4]);
        float hid[4] = { fmaxf(a.x, 0.f), fmaxf(a.y, 0.f),
                         fmaxf(a.z, 0.f), fmaxf(a.w, 0.f) };
        #pragma unroll
        for (int u = 0; u < 4; u++) {
            int j = j4*4 + u;
            float hv = hid[u];
            #pragma unroll
            for (int c4 = 0; c4 < 8; c4++) fma4(f[c4], hv, w24[j*8 + c4]);
        }
    }
    float r2[D];
    #pragma unroll
    for (int c4 = 0; c4 < 8; c4++) {
        r2[4*c4+0] = h1[4*c4+0] + f[c4].x; r2[4*c4+1] = h1[4*c4+1] + f[c4].y;
        r2[4*c4+2] = h1[4*c4+2] + f[c4].z; r2[4*c4+3] = h1[4*c4+3] + f[c4].w;
    }

    // LN2
    float mu2 = 0.f;
    #pragma unroll
    for (int c = 0; c < D; c++) mu2 += r2[c];
    mu2 *= (1.f / D);
    float var2 = 0.f;
    #pragma unroll
    for (int c = 0; c < D; c++) { float d0 = r2[c] - mu2; var2 += d0 * d0; }
    var2 *= (1.f / D);
    float rs2 = rsqrtf(var2 + 1e-5f);
    float out[D];
    #pragma unroll
    for (int c = 0; c < D; c++) out[c] = (r2[c] - mu2) * rs2 * s_g2[c] + s_be2[c];

    if (outp) {
        float4* op = (float4*)(outp + (size_t)t * D);
        #pragma unroll
        for (int c4 = 0; c4 < 8; c4++) {
            float4 v = { out[4*c4+0], out[4*c4+1], out[4*c4+2], out[4*c4+3] };
            op[c4] = v;
        }
    } else {
        float* dst = g_h + ((size_t)(t >> 5) << 10) + (t & 31);
        #pragma unroll
        for (int c = 0; c < D; c++) dst[c * 32] = out[c];
    }
}

extern "C" void kernel_launch(void* const* d_in, const int* in_sizes, int n_in,
                              void* d_out, int out_size)
{
    const float* x     = (const float*)d_in[0];
    const float* pos   = (const float*)d_in[1];
    // d_in[2] = batch (int32), trivially t / NPER — unused
    const float* w_in  = (const float*)d_in[3];
    const float* b_in  = (const float*)d_in[4];
    const float* w_pos = (const float*)d_in[5];
    const float* b_pos = (const float*)d_in[6];
    const float* wq    = (const float*)d_in[7];
    const float* bq    = (const float*)d_in[8];
    const float* wk    = (const float*)d_in[9];
    const float* bk    = (const float*)d_in[10];
    const float* wv    = (const float*)d_in[11];
    const float* bv    = (const float*)d_in[12];
    const float* wo    = (const float*)d_in[13];
    const float* bo    = (const float*)d_in[14];
    const float* g1    = (const float*)d_in[15];
    const float* be1   = (const float*)d_in[16];
    const float* w1    = (const float*)d_in[17];
    const float* bf1   = (const float*)d_in[18];
    const float* w2    = (const float*)d_in[19];
    const float* bf2   = (const float*)d_in[20];
    const float* g2    = (const float*)d_in[21];
    const float* be2   = (const float*)d_in[22];

    stem_kernel<<<T_PTS/256, 256>>>(x, pos, w_in, b_in, w_pos, b_pos);
    for (int l = 0; l < NL; l++) {
        reduce_kernel<<<dim3(T_PTS/(256*RPTS), NH), 256>>>(wk, bk, wv, bv, l);
        apply_kernel<<<T_PTS/256, 256>>>(wq, bq, wo, bo, g1, be1, w1, bf1,
                                         w2, bf2, g2, be2, l,
                                         (l == NL-1) ? (float*)d_out : nullptr);
    }
}

// round 4
// speedup vs baseline: 1.0088x; 1.0050x over previous
#include <cuda_runtime.h>
#include <math.h>

#define T_PTS 524288
#define NPER  32768
#define BG    16
#define CIN   16
#define D     32
#define NH    4
#define HD    8
#define NL    2
#define RPTS  16   // points per thread in reduce kernel

// 64 MB scratch for h, tiled: tile of 32 points, channel-major within tile:
// h(point p, chan c) at g_h[(p>>5)*1024 + c*32 + (p&31)]
__device__ float g_h[(size_t)T_PTS * D];
__device__ float g_kv[NL * BG * NH * HD * HD];   // 8192
__device__ float g_ks[NL * BG * NH * HD];        // 1024

__device__ __forceinline__ float phi(float x) {
    // elu(x)+1
    return x > 0.f ? x + 1.f : __expf(x);
}

__device__ __forceinline__ void fma4(float4& a, float s, const float4 w) {
    a.x += s * w.x; a.y += s * w.y; a.z += s * w.z; a.w += s * w.w;
}

// ---------------- stem: h = x@w_in + b_in + pos@w_pos + b_pos ----------------
__global__ __launch_bounds__(256) void stem_kernel(
    const float* __restrict__ x, const float* __restrict__ pos,
    const float* __restrict__ w_in, const float* __restrict__ b_in,
    const float* __restrict__ w_pos, const float* __restrict__ b_pos)
{
    __shared__ __align__(16) float s_win[CIN * D];
    __shared__ __align__(16) float s_wpos[4 * D];   // 3 rows used
    __shared__ __align__(16) float s_b[D];
    int tid = threadIdx.x;
    for (int i = tid; i < CIN * D; i += 256) s_win[i] = w_in[i];
    if (tid < 3 * D) s_wpos[tid] = w_pos[tid];
    if (tid < D)     s_b[tid]    = b_in[tid] + b_pos[tid];
    if (blockIdx.x == 0) {
        for (int i = tid; i < NL*BG*NH*HD*HD; i += 256) g_kv[i] = 0.f;
        for (int i = tid; i < NL*BG*NH*HD;    i += 256) g_ks[i] = 0.f;
    }
    __syncthreads();

    int t = blockIdx.x * 256 + tid;
    const float4* xp = (const float4*)(x + (size_t)t * CIN);
    float xx[CIN];
    #pragma unroll
    for (int i = 0; i < 4; i++) {
        float4 v = xp[i];
        xx[4*i+0] = v.x; xx[4*i+1] = v.y; xx[4*i+2] = v.z; xx[4*i+3] = v.w;
    }
    const float* pp = pos + (size_t)t * 3;
    float p3[3] = { pp[0], pp[1], pp[2] };

    float4 acc[8];
    const float4* b4 = (const float4*)s_b;
    #pragma unroll
    for (int j = 0; j < 8; j++) acc[j] = b4[j];

    const float4* w4 = (const float4*)s_win;      // [i*8 + j4]
    #pragma unroll
    for (int i = 0; i < CIN; i++) {
        float hi = xx[i];
        #pragma unroll
        for (int j = 0; j < 8; j++) fma4(acc[j], hi, w4[i*8 + j]);
    }
    const float4* wp4 = (const float4*)s_wpos;    // [i*8 + j4]
    #pragma unroll
    for (int i = 0; i < 3; i++) {
        float pi = p3[i];
        #pragma unroll
        for (int j = 0; j < 8; j++) fma4(acc[j], pi, wp4[i*8 + j]);
    }

    float* dst = g_h + ((size_t)(t >> 5) << 10) + (t & 31);
    #pragma unroll
    for (int j = 0; j < 8; j++) {
        dst[(4*j+0)*32] = acc[j].x;
        dst[(4*j+1)*32] = acc[j].y;
        dst[(4*j+2)*32] = acc[j].z;
        dst[(4*j+3)*32] = acc[j].w;
    }
}

// ---------------- reduce: kv[cloud][head] += k^T v ; ksum += k ----------------
__global__ __launch_bounds__(256) void reduce_kernel(
    const float* __restrict__ wk, const float* __restrict__ bk,
    const float* __restrict__ wv, const float* __restrict__ bv, int l)
{
    int head = blockIdx.y;
    __shared__ __align__(16) float s_wk[D * HD];
    __shared__ __align__(16) float s_wv[D * HD];
    __shared__ __align__(16) float s_bk[HD];
    __shared__ __align__(16) float s_bv[HD];
    int tid = threadIdx.x;
    if (tid < D * HD) {
        int i = tid / HD, j = tid % HD;
        s_wk[tid] = wk[l*D*D + i*D + head*HD + j];
        s_wv[tid] = wv[l*D*D + i*D + head*HD + j];
    }
    if (tid < HD) { s_bk[tid] = bk[l*D + head*HD + tid];
                    s_bv[tid] = bv[l*D + head*HD + tid]; }
    __syncthreads();

    int base  = blockIdx.x * (256 * RPTS);
    int cloud = blockIdx.x >> 3;   // 4096 points/block, 32768/cloud

    float kv[HD][HD];
    float ks[HD];
    #pragma unroll
    for (int a = 0; a < HD; a++) {
        ks[a] = 0.f;
        #pragma unroll
        for (int b = 0; b < HD; b++) kv[a][b] = 0.f;
    }

    const float4* wk4 = (const float4*)s_wk;   // [i*2 + j4]
    const float4* wv4 = (const float4*)s_wv;
    float4 bk0 = ((const float4*)s_bk)[0], bk1 = ((const float4*)s_bk)[1];
    float4 bv0 = ((const float4*)s_bv)[0], bv1 = ((const float4*)s_bv)[1];

    for (int it = 0; it < RPTS; it++) {
        int p = base + it * 256 + tid;
        const float* hp = g_h + ((size_t)(p >> 5) << 10) + (p & 31);
        float h[D];
        #pragma unroll
        for (int c = 0; c < D; c++) h[c] = hp[c * 32];

        float4 ka0 = bk0, ka1 = bk1, va0 = bv0, va1 = bv1;
        #pragma unroll
        for (int i = 0; i < D; i++) {
            float hi = h[i];
            fma4(ka0, hi, wk4[i*2+0]); fma4(ka1, hi, wk4[i*2+1]);
            fma4(va0, hi, wv4[i*2+0]); fma4(va1, hi, wv4[i*2+1]);
        }
        float kk[8] = { phi(ka0.x), phi(ka0.y), phi(ka0.z), phi(ka0.w),
                        phi(ka1.x), phi(ka1.y), phi(ka1.z), phi(ka1.w) };
        float vv[8] = { va0.x, va0.y, va0.z, va0.w, va1.x, va1.y, va1.z, va1.w };
        #pragma unroll
        for (int a = 0; a < 8; a++) {
            ks[a] += kk[a];
            #pragma unroll
            for (int b = 0; b < 8; b++) kv[a][b] += kk[a] * vv[b];
        }
    }

    // butterfly warp reduce + global atomics (lane 0)
    unsigned mask = 0xffffffffu;
    int lane = tid & 31;
    float* kvg = g_kv + ((size_t)((l*BG + cloud)*NH + head)) * 64;
    float* ksg = g_ks + ((size_t)((l*BG + cloud)*NH + head)) * 8;
    #pragma unroll
    for (int a = 0; a < 8; a++) {
        float s = ks[a];
        #pragma unroll
        for (int off = 16; off; off >>= 1) s += __shfl_xor_sync(mask, s, off);
        if (lane == 0) atomicAdd(&ksg[a], s);
        #pragma unroll
        for (int b = 0; b < 8; b++) {
            float v = kv[a][b];
            #pragma unroll
            for (int off = 16; off; off >>= 1) v += __shfl_xor_sync(mask, v, off);
            if (lane == 0) atomicAdd(&kvg[a*8 + b], v);
        }
    }
}

// ---------------- apply: q, attention, o-proj, LN1, FFN, LN2 ----------------
__global__ __launch_bounds__(256) void apply_kernel(
    const float* __restrict__ wq, const float* __restrict__ bq,
    const float* __restrict__ wo, const float* __restrict__ bo,
    const float* __restrict__ g1, const float* __restrict__ be1,
    const float* __restrict__ w1, const float* __restrict__ bf1,
    const float* __restrict__ w2, const float* __restrict__ bf2,
    const float* __restrict__ g2, const float* __restrict__ be2,
    int l, float* __restrict__ outp)
{
    __shared__ __align__(16) float s_wq[D*D];
    __shared__ __align__(16) float s_wo[D*D];
    __shared__ __align__(16) float s_w1[D*2*D];
    __shared__ __align__(16) float s_w2[2*D*D];
    __shared__ __align__(16) float s_kv[NH*HD*HD];
    __shared__ __align__(16) float s_ks[NH*HD];
    __shared__ __align__(16) float s_bq[D], s_bo[D], s_bf2[D];
    __shared__ __align__(16) float s_bf1[2*D];
    __shared__ __align__(16) float s_g1[D], s_be1[D], s_g2[D], s_be2[D];

    int tid = threadIdx.x;
    int t = blockIdx.x * 256 + tid;
    int cloud = t >> 15;

    for (int i = tid; i < 1024; i += 256) { s_wq[i] = wq[l*1024 + i]; s_wo[i] = wo[l*1024 + i]; }
    for (int i = tid; i < 2048; i += 256) { s_w1[i] = w1[l*2048 + i]; s_w2[i] = w2[l*2048 + i]; }
    if (tid < 32) {
        s_bq[tid]  = bq[l*32 + tid];  s_bo[tid]  = bo[l*32 + tid];
        s_bf2[tid] = bf2[l*32 + tid];
        s_g1[tid]  = g1[l*32 + tid];  s_be1[tid] = be1[l*32 + tid];
        s_g2[tid]  = g2[l*32 + tid];  s_be2[tid] = be2[l*32 + tid];
        s_ks[tid]  = g_ks[(size_t)(l*BG + cloud)*32 + tid];
    }
    if (tid < 64)  s_bf1[tid] = bf1[l*64 + tid];
    s_kv[tid] = g_kv[(size_t)(l*BG + cloud)*256 + tid];   // 256 entries
    __syncthreads();

    const float* hp = g_h + ((size_t)(t >> 5) << 10) + (t & 31);
    float h[D];
    #pragma unroll
    for (int c = 0; c < D; c++) h[c] = hp[c * 32];

    // q = phi(h @ wq + bq)
    float q[D];
    const float4* wq4 = (const float4*)s_wq;   // [c*8 + j4]
    #pragma unroll
    for (int j4 = 0; j4 < 8; j4++) {
        float4 a = ((const float4*)s_bq)[j4];
        #pragma unroll
        for (int c = 0; c < D; c++) fma4(a, h[c], wq4[c*8 + j4]);
        q[4*j4+0] = phi(a.x); q[4*j4+1] = phi(a.y);
        q[4*j4+2] = phi(a.z); q[4*j4+3] = phi(a.w);
    }

    // per-head attention: o = (q @ kv) / (q . ksum + eps)
    float o[D];
    #pragma unroll
    for (int hh = 0; hh < NH; hh++) {
        float zden = 1e-6f;
        #pragma unroll
        for (int d = 0; d < HD; d++) zden += q[hh*8 + d] * s_ks[hh*8 + d];
        float z = __fdividef(1.f, zden);
        const float4* kv4 = (const float4*)(s_kv + hh*64);  // [d*2 + e4]
        float4 a0 = {0,0,0,0}, a1 = {0,0,0,0};
        #pragma unroll
        for (int d = 0; d < HD; d++) {
            float qd = q[hh*8 + d];
            fma4(a0, qd, kv4[d*2+0]); fma4(a1, qd, kv4[d*2+1]);
        }
        o[hh*8+0] = a0.x*z; o[hh*8+1] = a0.y*z; o[hh*8+2] = a0.z*z; o[hh*8+3] = a0.w*z;
        o[hh*8+4] = a1.x*z; o[hh*8+5] = a1.y*z; o[hh*8+6] = a1.z*z; o[hh*8+7] = a1.w*z;
    }

    // o-proj + residual
    float r[D];
    const float4* wo4 = (const float4*)s_wo;   // [j*8 + c4]
    #pragma unroll
    for (int c4 = 0; c4 < 8; c4++) {
        float4 a = ((const float4*)s_bo)[c4];
        #pragma unroll
        for (int j = 0; j < D; j++) fma4(a, o[j], wo4[j*8 + c4]);
        r[4*c4+0] = h[4*c4+0] + a.x; r[4*c4+1] = h[4*c4+1] + a.y;
        r[4*c4+2] = h[4*c4+2] + a.z; r[4*c4+3] = h[4*c4+3] + a.w;
    }

    // LN1
    float mu = 0.f;
    #pragma unroll
    for (int c = 0; c < D; c++) mu += r[c];
    mu *= (1.f / D);
    float var = 0.f;
    #pragma unroll
    for (int c = 0; c < D; c++) { float d0 = r[c] - mu; var += d0 * d0; }
    var *= (1.f / D);
    float rs = rsqrtf(var + 1e-5f);
    float h1[D];
    #pragma unroll
    for (int c = 0; c < D; c++) h1[c] = (r[c] - mu) * rs * s_g1[c] + s_be1[c];

    // FFN: relu(h1 @ w1 + bf1) @ w2 + bf2
    float4 f[8];
    #pragma unroll
    for (int c4 = 0; c4 < 8; c4++) f[c4] = ((const float4*)s_bf2)[c4];
    const float4* w14 = (const float4*)s_w1;   // [c*16 + j4]
    const float4* w24 = (const float4*)s_w2;   // [j*8 + c4]
    #pragma unroll
    for (int j4 = 0; j4 < 16; j4++) {
        float4 a = ((const float4*)s_bf1)[j4];
        #pragma unroll
        for (int c = 0; c < D; c++) fma4(a, h1[c], w14[c*16 + j4]);
        float hid[4] = { fmaxf(a.x, 0.f), fmaxf(a.y, 0.f),
                         fmaxf(a.z, 0.f), fmaxf(a.w, 0.f) };
        #pragma unroll
        for (int u = 0; u < 4; u++) {
            int j = j4*4 + u;
            float hv = hid[u];
            #pragma unroll
            for (int c4 = 0; c4 < 8; c4++) fma4(f[c4], hv, w24[j*8 + c4]);
        }
    }
    float r2[D];
    #pragma unroll
    for (int c4 = 0; c4 < 8; c4++) {
        r2[4*c4+0] = h1[4*c4+0] + f[c4].x; r2[4*c4+1] = h1[4*c4+1] + f[c4].y;
        r2[4*c4+2] = h1[4*c4+2] + f[c4].z; r2[4*c4+3] = h1[4*c4+3] + f[c4].w;
    }

    // LN2
    float mu2 = 0.f;
    #pragma unroll
    for (int c = 0; c < D; c++) mu2 += r2[c];
    mu2 *= (1.f / D);
    float var2 = 0.f;
    #pragma unroll
    for (int c = 0; c < D; c++) { float d0 = r2[c] - mu2; var2 += d0 * d0; }
    var2 *= (1.f / D);
    float rs2 = rsqrtf(var2 + 1e-5f);
    float out[D];
    #pragma unroll
    for (int c = 0; c < D; c++) out[c] = (r2[c] - mu2) * rs2 * s_g2[c] + s_be2[c];

    if (outp) {
        float4* op = (float4*)(outp + (size_t)t * D);
        #pragma unroll
        for (int c4 = 0; c4 < 8; c4++) {
            float4 v = { out[4*c4+0], out[4*c4+1], out[4*c4+2], out[4*c4+3] };
            op[c4] = v;
        }
    } else {
        float* dst = g_h + ((size_t)(t >> 5) << 10) + (t & 31);
        #pragma unroll
        for (int c = 0; c < D; c++) dst[c * 32] = out[c];
    }
}

extern "C" void kernel_launch(void* const* d_in, const int* in_sizes, int n_in,
                              void* d_out, int out_size)
{
    const float* x     = (const float*)d_in[0];
    const float* pos   = (const float*)d_in[1];
    // d_in[2] = batch (int32), trivially t / NPER — unused
    const float* w_in  = (const float*)d_in[3];
    const float* b_in  = (const float*)d_in[4];
    const float* w_pos = (const float*)d_in[5];
    const float* b_pos = (const float*)d_in[6];
    const float* wq    = (const float*)d_in[7];
    const float* bq    = (const float*)d_in[8];
    const float* wk    = (const float*)d_in[9];
    const float* bk    = (const float*)d_in[10];
    const float* wv    = (const float*)d_in[11];
    const float* bv    = (const float*)d_in[12];
    const float* wo    = (const float*)d_in[13];
    const float* bo    = (const float*)d_in[14];
    const float* g1    = (const float*)d_in[15];
    const float* be1   = (const float*)d_in[16];
    const float* w1    = (const float*)d_in[17];
    const float* bf1   = (const float*)d_in[18];
    const float* w2    = (const float*)d_in[19];
    const float* bf2   = (const float*)d_in[20];
    const float* g2    = (const float*)d_in[21];
    const float* be2   = (const float*)d_in[22];

    stem_kernel<<<T_PTS/256, 256>>>(x, pos, w_in, b_in, w_pos, b_pos);
    for (int l = 0; l < NL; l++) {
        reduce_kernel<<<dim3(T_PTS/(256*RPTS), NH), 256>>>(wk, bk, wv, bv, l);
        apply_kernel<<<T_PTS/256, 256>>>(wq, bq, wo, bo, g1, be1, w1, bf1,
                                         w2, bf2, g2, be2, l,
                                         (l == NL-1) ? (float*)d_out : nullptr);
    }
}